// round 4
// baseline (speedup 1.0000x reference)
#include <cuda_runtime.h>

// KANModel fused forward, v2: occupancy + L1-wavefront restructure.
//
// Layer-0 as GEMM-like contraction z[b,o] = sum_{i,c} W[o,i,c] * f[b,i,c]
// with f = (silu(x), 8 cubic B-spline bases), W folded from (sb0, ssp0*coef0).
//
// Kernel 1: grid (32 batch-tiles x 8 i-chunks), 512 threads.
//   warp = 32 batches (lane = b), each lane register-tiles 4 outputs.
//   -> weight loads warp-uniform (1 wavefront), feature LDS stride-1.
//   Partial z written to __device__ scratch zpart[s][o][b] (disjoint, coalesced).
// Kernel 2: reduce 8 partials + bias0, layer-1 spline (64->1), sigmoid.

namespace {
constexpr int GI    = 5;
constexpr int NBAS  = 8;
constexpr int NC    = 9;       // silu + 8 bases
constexpr int DIN0  = 128;
constexpr int DOUT0 = 64;
constexpr int BATCH = 1024;
constexpr int TBAT  = 32;      // batch tile per block (k1)
constexpr int SPLIT = 8;       // i-chunks
constexpr int ICH   = DIN0 / SPLIT;  // 16 inputs per chunk
constexpr int BLK1  = 512;     // 16 warps = 64 outputs / 4-per-lane
constexpr int BLK2  = 256;
}

__device__ float g_zpart[SPLIT * DOUT0 * BATCH];   // [s][o][b], 2 MB

// Cox-de-Boor on 12 uniform-extended knots -> 8 cubic bases.
__device__ __forceinline__ void bspline8(float x, const float* t, float* out) {
    float B[11];
#pragma unroll
    for (int j = 0; j < 11; ++j)
        B[j] = (x >= t[j] && x < t[j + 1]) ? 1.0f : 0.0f;
#pragma unroll
    for (int kk = 1; kk <= 3; ++kk) {
#pragma unroll
        for (int j = 0; j < 11 - kk; ++j) {
            B[j] = (x - t[j]) / (t[j + kk] - t[j]) * B[j]
                 + (t[j + kk + 1] - x) / (t[j + kk + 1] - t[j + 1]) * B[j + 1];
        }
    }
#pragma unroll
    for (int j = 0; j < NBAS; ++j) out[j] = B[j];
}

__device__ __forceinline__ void make_knots(const float* __restrict__ g, float* t) {
    float h = (g[5] - g[0]) * (1.0f / GI);
    t[0] = g[0] - 3.f * h; t[1] = g[0] - 2.f * h; t[2] = g[0] - h;
#pragma unroll
    for (int j = 0; j < 6; ++j) t[3 + j] = g[j];
    t[9] = g[5] + h; t[10] = g[5] + 2.f * h; t[11] = g[5] + 3.f * h;
}

__device__ __forceinline__ float silu_f(float x) {
    return x * (1.0f / (1.0f + __expf(-x)));
}

// ---------------- Kernel 1: layer-0 partial contraction ----------------
__global__ __launch_bounds__(BLK1, 2) void kan_l0(
    const int*   __restrict__ uidx,  const int*   __restrict__ vidx,
    const float* __restrict__ emb_u, const float* __restrict__ emb_v,
    const float* __restrict__ grid0, const float* __restrict__ coef0,
    const float* __restrict__ sb0,   const float* __restrict__ ssp0)
{
    __shared__ float f[ICH * NC * TBAT];   // [i][c][b], b fastest (18 KB)
    const int tid  = threadIdx.x;
    const int lane = tid & 31;
    const int w    = tid >> 5;             // warp 0..15
    const int tile = blockIdx.x;           // batch tile
    const int s    = blockIdx.y;           // i-chunk

    float t0[12];
    {
        float g[6];
#pragma unroll
        for (int j = 0; j < 6; ++j) g[j] = grid0[j];
        make_knots(g, t0);
    }

    // Phase A: 512 features (32 b x 16 i), one per thread.
    {
        const int i  = tid >> 5;           // 0..15
        const int b  = tid & 31;
        const int ii = s * ICH + i;        // global input index
        const int gb = tile * TBAT + b;
        float x = (ii < 64) ? emb_u[uidx[gb] * 64 + ii]
                            : emb_v[vidx[gb] * 64 + (ii - 64)];
        float Bv[NBAS];
        bspline8(x, t0, Bv);
        f[(i * NC + 0) * TBAT + b] = silu_f(x);
#pragma unroll
        for (int c = 0; c < NBAS; ++c)
            f[(i * NC + 1 + c) * TBAT + b] = Bv[c];
    }
    __syncthreads();

    // Phase B: lane = batch, warp handles outputs {4w..4w+3}.
    float acc[4] = {0.f, 0.f, 0.f, 0.f};
    const float4* c4 = (const float4*)coef0;
#pragma unroll 2
    for (int i = 0; i < ICH; ++i) {
        float fv[NC];
#pragma unroll
        for (int c = 0; c < NC; ++c)
            fv[c] = f[(i * NC + c) * TBAT + lane];   // stride-1, conflict-free
        const int ii = s * ICH + i;
#pragma unroll
        for (int j = 0; j < 4; ++j) {
            const int n = (w * 4 + j) * DIN0 + ii;   // warp-uniform
            float sb  = sb0[n];
            float sp  = ssp0[n];
            float4 ca = c4[2 * n + 0];
            float4 cb = c4[2 * n + 1];
            float d = ca.x * fv[1];
            d = fmaf(ca.y, fv[2], d);
            d = fmaf(ca.z, fv[3], d);
            d = fmaf(ca.w, fv[4], d);
            d = fmaf(cb.x, fv[5], d);
            d = fmaf(cb.y, fv[6], d);
            d = fmaf(cb.z, fv[7], d);
            d = fmaf(cb.w, fv[8], d);
            acc[j] = fmaf(sb, fv[0], acc[j]);
            acc[j] = fmaf(sp, d, acc[j]);
        }
    }

    // Store partials: [s][o][b], lane-consecutive in b -> coalesced.
    const int gb = tile * TBAT + lane;
#pragma unroll
    for (int j = 0; j < 4; ++j) {
        const int o = w * 4 + j;
        g_zpart[(s * DOUT0 + o) * BATCH + gb] = acc[j];
    }
}

// ---------------- Kernel 2: reduce + bias0 + layer 1 + sigmoid ----------------
__global__ __launch_bounds__(BLK2) void kan_l1(
    const float* __restrict__ bias0,
    const float* __restrict__ grid1, const float* __restrict__ coef1,
    const float* __restrict__ sb1,   const float* __restrict__ ssp1,
    const float* __restrict__ bias1,
    float* __restrict__ out)
{
    __shared__ float red[8][32];
    const int lane = threadIdx.x & 31;
    const int grp  = threadIdx.x >> 5;          // 0..7 -> o-range
    const int b    = blockIdx.x * 32 + lane;

    float t1[12];
    {
        float g[6];
#pragma unroll
        for (int j = 0; j < 6; ++j) g[j] = grid1[j];
        make_knots(g, t1);
    }

    const float4* c4 = (const float4*)coef1;
    float part = 0.f;
#pragma unroll
    for (int k = 0; k < 8; ++k) {
        const int o = grp * 8 + k;
        float zb = bias0[o];
#pragma unroll
        for (int s = 0; s < SPLIT; ++s)
            zb += g_zpart[(s * DOUT0 + o) * BATCH + b];   // coalesced over lanes
        float Bv[NBAS];
        bspline8(zb, t1, Bv);
        float4 ca = c4[2 * o + 0];
        float4 cb = c4[2 * o + 1];
        float d = ca.x * Bv[0];
        d = fmaf(ca.y, Bv[1], d);
        d = fmaf(ca.z, Bv[2], d);
        d = fmaf(ca.w, Bv[3], d);
        d = fmaf(cb.x, Bv[4], d);
        d = fmaf(cb.y, Bv[5], d);
        d = fmaf(cb.z, Bv[6], d);
        d = fmaf(cb.w, Bv[7], d);
        part += sb1[o] * silu_f(zb) + ssp1[o] * d;
    }
    red[grp][lane] = part;
    __syncthreads();

    if (grp == 0) {
        float y = bias1[0];
#pragma unroll
        for (int g = 0; g < 8; ++g) y += red[g][lane];
        out[b] = 1.0f / (1.0f + __expf(-y));
    }
}

extern "C" void kernel_launch(void* const* d_in, const int* in_sizes, int n_in,
                              void* d_out, int out_size) {
    // Layout (16 inputs): 0:uidx 1:vidx 2:gun 3:sgus 4:emb_u 5:emb_v
    //   6:grid0 7:coef0 8:sb0 9:ssp0 10:bias0 11:grid1 12:coef1 13:sb1
    //   14:ssp1 15:bias1.  Robust to scalar materialization.
    const int s = (n_in >= 16) ? 2 : (n_in - 14);
    const int*   uidx  = (const int*)  d_in[0];
    const int*   vidx  = (const int*)  d_in[1];
    const float* embu  = (const float*)d_in[2 + s];
    const float* embv  = (const float*)d_in[3 + s];
    const float* grid0 = (const float*)d_in[4 + s];
    const float* coef0 = (const float*)d_in[5 + s];
    const float* sb0   = (const float*)d_in[6 + s];
    const float* ssp0  = (const float*)d_in[7 + s];
    const float* bias0 = (const float*)d_in[8 + s];
    const float* grid1 = (const float*)d_in[9 + s];
    const float* coef1 = (const float*)d_in[10 + s];
    const float* sb1   = (const float*)d_in[11 + s];
    const float* ssp1  = (const float*)d_in[12 + s];
    const float* bias1 = (const float*)d_in[13 + s];
    float* outp = (float*)d_out;

    dim3 g1(BATCH / TBAT, SPLIT);     // 32 x 8 = 256 blocks
    kan_l0<<<g1, BLK1>>>(uidx, vidx, embu, embv, grid0, coef0, sb0, ssp0);
    kan_l1<<<BATCH / 32, BLK2>>>(bias0, grid1, coef1, sb1, ssp1, bias1, outp);
}

// round 5
// speedup vs baseline: 1.0295x; 1.0295x over previous
#include <cuda_runtime.h>

// KANModel fused forward, v3: ONE kernel.
//   Layer-0 contraction split 8-way over inputs (256 blocks x 256 thr),
//   partials to __device__ scratch; the LAST block of each batch-tile
//   (atomic counter) runs the layer-1 epilogue for that tile in-place.
// Rationale (R4 ncu): the separate 32-block epilogue kernel was the
// bottleneck (42us, all pipes idle: low occupancy + spilled 8x-unrolled
// bspline). Fuse it, keep one bspline live, keep all SMs busy.

namespace {
constexpr int GI    = 5;
constexpr int NBAS  = 8;
constexpr int NC    = 9;                 // silu + 8 bases
constexpr int DIN0  = 128;
constexpr int DOUT0 = 64;
constexpr int BATCH = 1024;
constexpr int TBAT  = 32;                // batches per tile (lane = batch)
constexpr int SPLIT = 8;                 // i-chunks
constexpr int ICH   = DIN0 / SPLIT;      // 16
constexpr int BLK   = 256;               // 8 warps; warp handles 8 outputs
constexpr int NTILE = BATCH / TBAT;      // 32
}

__device__ float    g_zpart[SPLIT * DOUT0 * BATCH];  // [s][o][b], 2 MB
__device__ unsigned g_cnt[NTILE];                    // zero-init; reset each pass

// Cox-de-Boor on 12 uniform-extended knots -> 8 cubic bases.
__device__ __forceinline__ void bspline8(float x, const float* t, float* out) {
    float B[11];
#pragma unroll
    for (int j = 0; j < 11; ++j)
        B[j] = (x >= t[j] && x < t[j + 1]) ? 1.0f : 0.0f;
#pragma unroll
    for (int kk = 1; kk <= 3; ++kk) {
#pragma unroll
        for (int j = 0; j < 11 - kk; ++j) {
            B[j] = (x - t[j]) / (t[j + kk] - t[j]) * B[j]
                 + (t[j + kk + 1] - x) / (t[j + kk + 1] - t[j + 1]) * B[j + 1];
        }
    }
#pragma unroll
    for (int j = 0; j < NBAS; ++j) out[j] = B[j];
}

__device__ __forceinline__ void make_knots(const float* __restrict__ g, float* t) {
    float h = (g[5] - g[0]) * (1.0f / GI);
    t[0] = g[0] - 3.f * h; t[1] = g[0] - 2.f * h; t[2] = g[0] - h;
#pragma unroll
    for (int j = 0; j < 6; ++j) t[3 + j] = g[j];
    t[9] = g[5] + h; t[10] = g[5] + 2.f * h; t[11] = g[5] + 3.f * h;
}

__device__ __forceinline__ float silu_f(float x) {
    return x * (1.0f / (1.0f + __expf(-x)));
}

__global__ __launch_bounds__(BLK) void kan_v3(
    const int*   __restrict__ uidx,  const int*   __restrict__ vidx,
    const float* __restrict__ emb_u, const float* __restrict__ emb_v,
    const float* __restrict__ grid0, const float* __restrict__ coef0,
    const float* __restrict__ sb0,   const float* __restrict__ ssp0,
    const float* __restrict__ bias0,
    const float* __restrict__ grid1, const float* __restrict__ coef1,
    const float* __restrict__ sb1,   const float* __restrict__ ssp1,
    const float* __restrict__ bias1,
    float* __restrict__ out)
{
    __shared__ float f[ICH * NC * TBAT];   // [i][c][b], b fastest (18 KB)
    __shared__ float red[8][TBAT];
    __shared__ int   s_last;

    const int tid  = threadIdx.x;
    const int lane = tid & 31;
    const int w    = tid >> 5;             // warp 0..7
    const int tile = blockIdx.x;           // batch tile 0..31
    const int s    = blockIdx.y;           // i-chunk 0..7
    const int gb   = tile * TBAT + lane;

    // ---- knots (all grid rows identical by construction) ----
    float t0[12];
    {
        float g[6];
#pragma unroll
        for (int j = 0; j < 6; ++j) g[j] = grid0[j];
        make_knots(g, t0);
    }

    // ---- Phase A: 512 features (32 b x 16 i), 2 per thread ----
#pragma unroll
    for (int r = 0; r < 2; ++r) {
        const int fi = tid + r * BLK;
        const int i  = fi >> 5;            // 0..15
        const int b  = fi & 31;
        const int ii = s * ICH + i;
        const int gbb = tile * TBAT + b;
        float x = (ii < 64) ? emb_u[uidx[gbb] * 64 + ii]
                            : emb_v[vidx[gbb] * 64 + (ii - 64)];
        float Bv[NBAS];
        bspline8(x, t0, Bv);
        f[(i * NC + 0) * TBAT + b] = silu_f(x);
#pragma unroll
        for (int c = 0; c < NBAS; ++c)
            f[(i * NC + 1 + c) * TBAT + b] = Bv[c];
    }
    __syncthreads();

    // ---- Phase B: lane = batch, warp w handles outputs {8w..8w+7} ----
    float acc[8] = {0.f, 0.f, 0.f, 0.f, 0.f, 0.f, 0.f, 0.f};
    {
        const float4* c4 = (const float4*)coef0;
#pragma unroll 2
        for (int i = 0; i < ICH; ++i) {
            float fv[NC];
#pragma unroll
            for (int c = 0; c < NC; ++c)
                fv[c] = f[(i * NC + c) * TBAT + lane];  // stride-1, no conflicts
            const int ii = s * ICH + i;
#pragma unroll
            for (int k = 0; k < 8; ++k) {
                const int n = (w * 8 + k) * DIN0 + ii;  // warp-uniform
                float sb  = sb0[n];
                float sp  = ssp0[n];
                float4 ca = c4[2 * n + 0];
                float4 cb = c4[2 * n + 1];
                float d = ca.x * fv[1];
                d = fmaf(ca.y, fv[2], d);
                d = fmaf(ca.z, fv[3], d);
                d = fmaf(ca.w, fv[4], d);
                d = fmaf(cb.x, fv[5], d);
                d = fmaf(cb.y, fv[6], d);
                d = fmaf(cb.z, fv[7], d);
                d = fmaf(cb.w, fv[8], d);
                acc[k] = fmaf(sb, fv[0], acc[k]);
                acc[k] = fmaf(sp, d, acc[k]);
            }
        }
    }
#pragma unroll
    for (int k = 0; k < 8; ++k)
        g_zpart[(s * DOUT0 + (w * 8 + k)) * BATCH + gb] = acc[k];

    // ---- publish + elect last block of this tile ----
    __threadfence();
    __syncthreads();
    if (tid == 0) {
        unsigned old = atomicAdd(&g_cnt[tile], 1u);
        s_last = (old == SPLIT - 1) ? 1 : 0;
    }
    __syncthreads();
    if (!s_last) return;
    __threadfence();

    // ---- Epilogue (last block only): reduce + bias0 + layer 1 + sigmoid ----
    {
        float t1[12];
        {
            float g[6];
#pragma unroll
            for (int j = 0; j < 6; ++j) g[j] = grid1[j];
            make_knots(g, t1);
        }
        const float4* c4 = (const float4*)coef1;
        float part = 0.f;
#pragma unroll 1                           // keep ONE bspline live -> no spills
        for (int k = 0; k < 8; ++k) {
            const int o = w * 8 + k;
            float zb = bias0[o];
#pragma unroll
            for (int ss = 0; ss < SPLIT; ++ss)
                zb += g_zpart[(ss * DOUT0 + o) * BATCH + gb];  // coalesced
            float Bv[NBAS];
            bspline8(zb, t1, Bv);
            float4 ca = c4[2 * o + 0];
            float4 cb = c4[2 * o + 1];
            float d = ca.x * Bv[0];
            d = fmaf(ca.y, Bv[1], d);
            d = fmaf(ca.z, Bv[2], d);
            d = fmaf(ca.w, Bv[3], d);
            d = fmaf(cb.x, Bv[4], d);
            d = fmaf(cb.y, Bv[5], d);
            d = fmaf(cb.z, Bv[6], d);
            d = fmaf(cb.w, Bv[7], d);
            part += sb1[o] * silu_f(zb) + ssp1[o] * d;
        }
        red[w][lane] = part;
        __syncthreads();
        if (w == 0) {
            float y = bias1[0];
#pragma unroll
            for (int g = 0; g < 8; ++g) y += red[g][lane];
            out[gb] = 1.0f / (1.0f + __expf(-y));
        }
        // reset counter for the next (stream-serialized) graph replay
        if (tid == 0) g_cnt[tile] = 0;
    }
}

extern "C" void kernel_launch(void* const* d_in, const int* in_sizes, int n_in,
                              void* d_out, int out_size) {
    // Layout (16 inputs): 0:uidx 1:vidx 2:gun 3:sgus 4:emb_u 5:emb_v
    //   6:grid0 7:coef0 8:sb0 9:ssp0 10:bias0 11:grid1 12:coef1 13:sb1
    //   14:ssp1 15:bias1.  Robust to scalar materialization.
    const int s = (n_in >= 16) ? 2 : (n_in - 14);
    const int*   uidx  = (const int*)  d_in[0];
    const int*   vidx  = (const int*)  d_in[1];
    const float* embu  = (const float*)d_in[2 + s];
    const float* embv  = (const float*)d_in[3 + s];
    const float* grid0 = (const float*)d_in[4 + s];
    const float* coef0 = (const float*)d_in[5 + s];
    const float* sb0   = (const float*)d_in[6 + s];
    const float* ssp0  = (const float*)d_in[7 + s];
    const float* bias0 = (const float*)d_in[8 + s];
    const float* grid1 = (const float*)d_in[9 + s];
    const float* coef1 = (const float*)d_in[10 + s];
    const float* sb1   = (const float*)d_in[11 + s];
    const float* ssp1  = (const float*)d_in[12 + s];
    const float* bias1 = (const float*)d_in[13 + s];
    float* outp = (float*)d_out;

    dim3 g(NTILE, SPLIT);   // 32 x 8 = 256 blocks
    kan_v3<<<g, BLK>>>(uidx, vidx, embu, embv,
                       grid0, coef0, sb0, ssp0, bias0,
                       grid1, coef1, sb1, ssp1, bias1, outp);
}

// round 6
// speedup vs baseline: 1.6332x; 1.5864x over previous
#include <cuda_runtime.h>

// KANModel fused forward, v4: division-free uniform-knot B-splines.
// R5 insight: all prior variants were dominated by fp32-division latency
// chains inside Cox-de-Boor (27 divs per bspline call). Knots are uniform,
// so with u = (x - t0)/h the recurrence needs only constant multiplies.
//
// Structure: layer-0 contraction split 16-way over inputs (512 blocks x 256
// thr); partials to __device__ scratch; last block per batch-tile (atomic
// counter) runs the layer-1 epilogue + sigmoid in-place.

namespace {
constexpr int NBAS  = 8;
constexpr int NC    = 9;                 // silu + 8 bases
constexpr int DIN0  = 128;
constexpr int DOUT0 = 64;
constexpr int BATCH = 1024;
constexpr int TBAT  = 32;                // batches per tile (lane = batch)
constexpr int SPLIT = 16;                // i-chunks
constexpr int ICH   = DIN0 / SPLIT;      // 8
constexpr int BLK   = 256;               // 8 warps; warp handles 8 outputs
constexpr int NTILE = BATCH / TBAT;      // 32
}

__device__ float    g_zpart[SPLIT * DOUT0 * BATCH];  // [s][o][b], 4 MB
__device__ unsigned g_cnt[NTILE];                    // zero-init; reset per pass

// Division-free cubic Cox-de-Boor on uniform knots.
// u = (x - t0)/h where t0 = grid[0] - 3h. Valid support: u in [0, 11).
__device__ __forceinline__ void bspline8u(float u, float* out) {
    float B[11];
#pragma unroll
    for (int j = 0; j < 11; ++j)
        B[j] = (u >= (float)j && u < (float)(j + 1)) ? 1.0f : 0.0f;
#pragma unroll
    for (int j = 0; j < 10; ++j)
        B[j] = (u - (float)j) * B[j] + ((float)(j + 2) - u) * B[j + 1];
#pragma unroll
    for (int j = 0; j < 9; ++j)
        B[j] = 0.5f * ((u - (float)j) * B[j] + ((float)(j + 3) - u) * B[j + 1]);
#pragma unroll
    for (int j = 0; j < 8; ++j)
        out[j] = (1.0f / 3.0f) * ((u - (float)j) * B[j] + ((float)(j + 4) - u) * B[j + 1]);
}

__device__ __forceinline__ float silu_f(float x) {
    return x * (1.0f / (1.0f + __expf(-x)));
}

__global__ __launch_bounds__(BLK) void kan_v4(
    const int*   __restrict__ uidx,  const int*   __restrict__ vidx,
    const float* __restrict__ emb_u, const float* __restrict__ emb_v,
    const float* __restrict__ grid0, const float* __restrict__ coef0,
    const float* __restrict__ sb0,   const float* __restrict__ ssp0,
    const float* __restrict__ bias0,
    const float* __restrict__ grid1, const float* __restrict__ coef1,
    const float* __restrict__ sb1,   const float* __restrict__ ssp1,
    const float* __restrict__ bias1,
    float* __restrict__ out)
{
    __shared__ float f[ICH * NC * TBAT];   // [i][c][b], b fastest (9 KB)
    __shared__ float red[8][TBAT];
    __shared__ int   s_last;

    const int tid  = threadIdx.x;
    const int lane = tid & 31;
    const int w    = tid >> 5;             // warp 0..7
    const int tile = blockIdx.x;           // batch tile 0..31
    const int s    = blockIdx.y;           // i-chunk 0..15
    const int gb   = tile * TBAT + lane;

    // uniform-knot params for layer 0 (all grid rows identical)
    const float g0lo = grid0[0], g0hi = grid0[5];
    const float h0  = (g0hi - g0lo) * 0.2f;
    const float rh0 = 1.0f / h0;
    const float t00 = g0lo - 3.0f * h0;

    // ---- Phase A: 256 features (32 b x 8 i), 1 per thread ----
    {
        const int i  = tid >> 5;           // 0..7
        const int b  = tid & 31;
        const int ii = s * ICH + i;
        const int gbb = tile * TBAT + b;
        float x = (ii < 64) ? emb_u[uidx[gbb] * 64 + ii]
                            : emb_v[vidx[gbb] * 64 + (ii - 64)];
        float Bv[NBAS];
        bspline8u((x - t00) * rh0, Bv);
        f[(i * NC + 0) * TBAT + b] = silu_f(x);
#pragma unroll
        for (int c = 0; c < NBAS; ++c)
            f[(i * NC + 1 + c) * TBAT + b] = Bv[c];
    }
    __syncthreads();

    // ---- Phase B: lane = batch, warp w handles outputs {8w..8w+7} ----
    float acc[8] = {0.f, 0.f, 0.f, 0.f, 0.f, 0.f, 0.f, 0.f};
    {
        const float4* c4 = (const float4*)coef0;
#pragma unroll 2
        for (int i = 0; i < ICH; ++i) {
            float fv[NC];
#pragma unroll
            for (int c = 0; c < NC; ++c)
                fv[c] = f[(i * NC + c) * TBAT + lane];  // stride-1, no conflicts
            const int ii = s * ICH + i;
#pragma unroll
            for (int k = 0; k < 8; ++k) {
                const int n = (w * 8 + k) * DIN0 + ii;  // warp-uniform
                float sb  = sb0[n];
                float sp  = ssp0[n];
                float4 ca = c4[2 * n + 0];
                float4 cb = c4[2 * n + 1];
                float d = ca.x * fv[1];
                d = fmaf(ca.y, fv[2], d);
                d = fmaf(ca.z, fv[3], d);
                d = fmaf(ca.w, fv[4], d);
                d = fmaf(cb.x, fv[5], d);
                d = fmaf(cb.y, fv[6], d);
                d = fmaf(cb.z, fv[7], d);
                d = fmaf(cb.w, fv[8], d);
                acc[k] = fmaf(sb, fv[0], acc[k]);
                acc[k] = fmaf(sp, d, acc[k]);
            }
        }
    }
#pragma unroll
    for (int k = 0; k < 8; ++k)
        g_zpart[(s * DOUT0 + (w * 8 + k)) * BATCH + gb] = acc[k];

    // ---- publish + elect last block of this tile ----
    __threadfence();
    __syncthreads();
    if (tid == 0) {
        unsigned old = atomicAdd(&g_cnt[tile], 1u);
        s_last = (old == SPLIT - 1) ? 1 : 0;
    }
    __syncthreads();
    if (!s_last) return;
    __threadfence();

    // ---- Epilogue (last block of tile): reduce + bias0 + layer 1 + sigmoid ----
    {
        const float g1lo = grid1[0], g1hi = grid1[5];
        const float h1  = (g1hi - g1lo) * 0.2f;
        const float rh1 = 1.0f / h1;
        const float t10 = g1lo - 3.0f * h1;

        const float4* c4 = (const float4*)coef1;
        float part = 0.f;
#pragma unroll 2
        for (int k = 0; k < 8; ++k) {
            const int o = w * 8 + k;
            float zb = bias0[o];
#pragma unroll
            for (int ss = 0; ss < SPLIT; ++ss)
                zb += g_zpart[(ss * DOUT0 + o) * BATCH + gb];  // coalesced
            float Bv[NBAS];
            bspline8u((zb - t10) * rh1, Bv);
            float4 ca = c4[2 * o + 0];
            float4 cb = c4[2 * o + 1];
            float d = ca.x * Bv[0];
            d = fmaf(ca.y, Bv[1], d);
            d = fmaf(ca.z, Bv[2], d);
            d = fmaf(ca.w, Bv[3], d);
            d = fmaf(cb.x, Bv[4], d);
            d = fmaf(cb.y, Bv[5], d);
            d = fmaf(cb.z, Bv[6], d);
            d = fmaf(cb.w, Bv[7], d);
            part += sb1[o] * silu_f(zb) + ssp1[o] * d;
        }
        red[w][lane] = part;
        __syncthreads();
        if (w == 0) {
            float y = bias1[0];
#pragma unroll
            for (int g = 0; g < 8; ++g) y += red[g][lane];
            out[gb] = 1.0f / (1.0f + __expf(-y));
        }
        if (tid == 0) g_cnt[tile] = 0;   // reset for next graph replay
    }
}

extern "C" void kernel_launch(void* const* d_in, const int* in_sizes, int n_in,
                              void* d_out, int out_size) {
    // Layout (16 inputs): 0:uidx 1:vidx 2:gun 3:sgus 4:emb_u 5:emb_v
    //   6:grid0 7:coef0 8:sb0 9:ssp0 10:bias0 11:grid1 12:coef1 13:sb1
    //   14:ssp1 15:bias1.  Robust to scalar materialization.
    const int s = (n_in >= 16) ? 2 : (n_in - 14);
    const int*   uidx  = (const int*)  d_in[0];
    const int*   vidx  = (const int*)  d_in[1];
    const float* embu  = (const float*)d_in[2 + s];
    const float* embv  = (const float*)d_in[3 + s];
    const float* grid0 = (const float*)d_in[4 + s];
    const float* coef0 = (const float*)d_in[5 + s];
    const float* sb0   = (const float*)d_in[6 + s];
    const float* ssp0  = (const float*)d_in[7 + s];
    const float* bias0 = (const float*)d_in[8 + s];
    const float* grid1 = (const float*)d_in[9 + s];
    const float* coef1 = (const float*)d_in[10 + s];
    const float* sb1   = (const float*)d_in[11 + s];
    const float* ssp1  = (const float*)d_in[12 + s];
    const float* bias1 = (const float*)d_in[13 + s];
    float* outp = (float*)d_out;

    dim3 g(NTILE, SPLIT);   // 32 x 16 = 512 blocks
    kan_v4<<<g, BLK>>>(uidx, vidx, embu, embv,
                       grid0, coef0, sb0, ssp0, bias0,
                       grid1, coef1, sb1, ssp1, bias1, outp);
}

// round 7
// speedup vs baseline: 1.9276x; 1.1803x over previous
#include <cuda_runtime.h>

// KANModel fused forward, v5: SMEM-staged pre-folded weights.
// R6 insight: inner loop issued 32 warp-uniform LDGs per i-iter that hit L2
// (~234cyc) -- the dominant stall. Stage the block's weight slice into SMEM
// once (coalesced, pre-scaling coef by ssp), so the mainloop is pure LDS+FMA.

namespace {
constexpr int NBAS  = 8;
constexpr int NC    = 9;                 // silu + 8 bases
constexpr int DIN0  = 128;
constexpr int DOUT0 = 64;
constexpr int BATCH = 1024;
constexpr int TBAT  = 32;                // batches per tile (lane = batch)
constexpr int SPLIT = 16;                // i-chunks
constexpr int ICH   = DIN0 / SPLIT;      // 8
constexpr int BLK   = 256;               // 8 warps; warp handles 8 outputs
constexpr int NTILE = BATCH / TBAT;      // 32
}

__device__ float    g_zpart[SPLIT * DOUT0 * BATCH];  // [s][o][b], 4 MB
__device__ unsigned g_cnt[NTILE];                    // zero-init; reset per pass

// Division-free cubic Cox-de-Boor on uniform knots, u = (x - t0)/h in [0,11).
__device__ __forceinline__ void bspline8u(float u, float* out) {
    float B[11];
#pragma unroll
    for (int j = 0; j < 11; ++j)
        B[j] = (u >= (float)j && u < (float)(j + 1)) ? 1.0f : 0.0f;
#pragma unroll
    for (int j = 0; j < 10; ++j)
        B[j] = (u - (float)j) * B[j] + ((float)(j + 2) - u) * B[j + 1];
#pragma unroll
    for (int j = 0; j < 9; ++j)
        B[j] = 0.5f * ((u - (float)j) * B[j] + ((float)(j + 3) - u) * B[j + 1]);
#pragma unroll
    for (int j = 0; j < 8; ++j)
        out[j] = (1.0f / 3.0f) * ((u - (float)j) * B[j] + ((float)(j + 4) - u) * B[j + 1]);
}

__device__ __forceinline__ float silu_f(float x) {
    return x * (1.0f / (1.0f + __expf(-x)));
}

__global__ __launch_bounds__(BLK) void kan_v5(
    const int*   __restrict__ uidx,  const int*   __restrict__ vidx,
    const float* __restrict__ emb_u, const float* __restrict__ emb_v,
    const float* __restrict__ grid0, const float* __restrict__ coef0,
    const float* __restrict__ sb0,   const float* __restrict__ ssp0,
    const float* __restrict__ bias0,
    const float* __restrict__ grid1, const float* __restrict__ coef1,
    const float* __restrict__ sb1,   const float* __restrict__ ssp1,
    const float* __restrict__ bias1,
    float* __restrict__ out)
{
    __shared__ float  f[ICH * NC * TBAT];        // [i][c][b], b fastest (9 KB)
    __shared__ float4 wc[ICH * DOUT0 * 2];       // folded coefs [i][o][2] (16 KB)
    __shared__ float  wb[ICH * DOUT0];           // sb           [i][o]    (2 KB)
    __shared__ float  red[8][TBAT];
    __shared__ int    s_last;

    const int tid  = threadIdx.x;
    const int lane = tid & 31;
    const int w    = tid >> 5;             // warp 0..7
    const int tile = blockIdx.x;           // batch tile 0..31
    const int s    = blockIdx.y;           // i-chunk 0..15
    const int gb   = tile * TBAT + lane;

    // uniform-knot params for layer 0 (all grid rows identical)
    const float g0lo = grid0[0], g0hi = grid0[5];
    const float h0  = (g0hi - g0lo) * 0.2f;
    const float rh0 = 1.0f / h0;
    const float t00 = g0lo - 3.0f * h0;

    // ---- Stage weights: 512 (o,i) pairs, 2 per thread, pre-fold ssp ----
    {
        const float4* c4 = (const float4*)coef0;
#pragma unroll
        for (int r = 0; r < 2; ++r) {
            const int p  = tid + r * BLK;   // 0..511
            const int o  = p >> 3;          // 0..63
            const int i  = p & 7;           // 0..7
            const int n  = o * DIN0 + (s * ICH + i);
            const float sp = ssp0[n];
            float4 ca = c4[2 * n + 0];
            float4 cb = c4[2 * n + 1];
            ca.x *= sp; ca.y *= sp; ca.z *= sp; ca.w *= sp;
            cb.x *= sp; cb.y *= sp; cb.z *= sp; cb.w *= sp;
            wc[(i * DOUT0 + o) * 2 + 0] = ca;
            wc[(i * DOUT0 + o) * 2 + 1] = cb;
            wb[i * DOUT0 + o] = sb0[n];
        }
    }

    // ---- Phase A: 256 features (32 b x 8 i), 1 per thread ----
    {
        const int i  = tid >> 5;           // 0..7
        const int b  = tid & 31;
        const int ii = s * ICH + i;
        const int gbb = tile * TBAT + b;
        float x = (ii < 64) ? emb_u[uidx[gbb] * 64 + ii]
                            : emb_v[vidx[gbb] * 64 + (ii - 64)];
        float Bv[NBAS];
        bspline8u((x - t00) * rh0, Bv);
        f[(i * NC + 0) * TBAT + b] = silu_f(x);
#pragma unroll
        for (int c = 0; c < NBAS; ++c)
            f[(i * NC + 1 + c) * TBAT + b] = Bv[c];
    }
    __syncthreads();

    // ---- Phase B: lane = batch, warp w handles outputs {8w..8w+7} ----
    // Pure LDS + FMA: weights are uniform broadcasts from SMEM.
    float acc[8] = {0.f, 0.f, 0.f, 0.f, 0.f, 0.f, 0.f, 0.f};
#pragma unroll 2
    for (int i = 0; i < ICH; ++i) {
        float fv[NC];
#pragma unroll
        for (int c = 0; c < NC; ++c)
            fv[c] = f[(i * NC + c) * TBAT + lane];  // stride-1, no conflicts
#pragma unroll
        for (int k = 0; k < 8; ++k) {
            const int o = w * 8 + k;                // warp-uniform
            const float4 ca = wc[(i * DOUT0 + o) * 2 + 0];
            const float4 cb = wc[(i * DOUT0 + o) * 2 + 1];
            float a = acc[k];
            a = fmaf(wb[i * DOUT0 + o], fv[0], a);
            a = fmaf(ca.x, fv[1], a);
            a = fmaf(ca.y, fv[2], a);
            a = fmaf(ca.z, fv[3], a);
            a = fmaf(ca.w, fv[4], a);
            a = fmaf(cb.x, fv[5], a);
            a = fmaf(cb.y, fv[6], a);
            a = fmaf(cb.z, fv[7], a);
            a = fmaf(cb.w, fv[8], a);
            acc[k] = a;
        }
    }
#pragma unroll
    for (int k = 0; k < 8; ++k)
        g_zpart[(s * DOUT0 + (w * 8 + k)) * BATCH + gb] = acc[k];

    // ---- publish + elect last block of this tile ----
    __threadfence();
    __syncthreads();
    if (tid == 0) {
        unsigned old = atomicAdd(&g_cnt[tile], 1u);
        s_last = (old == SPLIT - 1) ? 1 : 0;
    }
    __syncthreads();
    if (!s_last) return;
    __threadfence();

    // ---- Epilogue (last block of tile): reduce + bias0 + layer 1 + sigmoid ----
    {
        const float g1lo = grid1[0], g1hi = grid1[5];
        const float h1  = (g1hi - g1lo) * 0.2f;
        const float rh1 = 1.0f / h1;
        const float t10 = g1lo - 3.0f * h1;

        const float4* c4 = (const float4*)coef1;
        float part = 0.f;
#pragma unroll 2
        for (int k = 0; k < 8; ++k) {
            const int o = w * 8 + k;
            float zb = bias0[o];
#pragma unroll
            for (int ss = 0; ss < SPLIT; ++ss)
                zb += g_zpart[(ss * DOUT0 + o) * BATCH + gb];  // coalesced
            float Bv[NBAS];
            bspline8u((zb - t10) * rh1, Bv);
            float4 ca = c4[2 * o + 0];
            float4 cb = c4[2 * o + 1];
            float d = ca.x * Bv[0];
            d = fmaf(ca.y, Bv[1], d);
            d = fmaf(ca.z, Bv[2], d);
            d = fmaf(ca.w, Bv[3], d);
            d = fmaf(cb.x, Bv[4], d);
            d = fmaf(cb.y, Bv[5], d);
            d = fmaf(cb.z, Bv[6], d);
            d = fmaf(cb.w, Bv[7], d);
            part += sb1[o] * silu_f(zb) + ssp1[o] * d;
        }
        red[w][lane] = part;
        __syncthreads();
        if (w == 0) {
            float y = bias1[0];
#pragma unroll
            for (int g = 0; g < 8; ++g) y += red[g][lane];
            out[gb] = 1.0f / (1.0f + __expf(-y));
        }
        if (tid == 0) g_cnt[tile] = 0;   // reset for next graph replay
    }
}

extern "C" void kernel_launch(void* const* d_in, const int* in_sizes, int n_in,
                              void* d_out, int out_size) {
    // Layout (16 inputs): 0:uidx 1:vidx 2:gun 3:sgus 4:emb_u 5:emb_v
    //   6:grid0 7:coef0 8:sb0 9:ssp0 10:bias0 11:grid1 12:coef1 13:sb1
    //   14:ssp1 15:bias1.  Robust to scalar materialization.
    const int s = (n_in >= 16) ? 2 : (n_in - 14);
    const int*   uidx  = (const int*)  d_in[0];
    const int*   vidx  = (const int*)  d_in[1];
    const float* embu  = (const float*)d_in[2 + s];
    const float* embv  = (const float*)d_in[3 + s];
    const float* grid0 = (const float*)d_in[4 + s];
    const float* coef0 = (const float*)d_in[5 + s];
    const float* sb0   = (const float*)d_in[6 + s];
    const float* ssp0  = (const float*)d_in[7 + s];
    const float* bias0 = (const float*)d_in[8 + s];
    const float* grid1 = (const float*)d_in[9 + s];
    const float* coef1 = (const float*)d_in[10 + s];
    const float* sb1   = (const float*)d_in[11 + s];
    const float* ssp1  = (const float*)d_in[12 + s];
    const float* bias1 = (const float*)d_in[13 + s];
    float* outp = (float*)d_out;

    dim3 g(NTILE, SPLIT);   // 32 x 16 = 512 blocks
    kan_v5<<<g, BLK>>>(uidx, vidx, embu, embv,
                       grid0, coef0, sb0, ssp0, bias0,
                       grid1, coef1, sb1, ssp1, bias1, outp);
}